// round 3
// baseline (speedup 1.0000x reference)
#include <cuda_runtime.h>
#include <math.h>

// SCPDTLoss on GB300/B200 (sm_100a/sm_103a)
//
// Math reduction: with w = 1/sigma, the lower triangle of G = [V|r]^T D^-1 [V|r]:
//   G[k][j], k,j<16  -> V^T D^-1 V          (136 entries)
//   G[16][j], j<16   -> u = V^T D^-1 r      (16 entries)
//   G[16][16]        -> r^T D^-1 r          (1 entry)
// quad_form = rDr - ||L^{-1} u||^2  (M = G_vv + (1+jitter) I = L L^T)
// -> ONE pass over V, ONE forward solve.
//
// Phase 1 uses packed fma.rn.f32x2 (FFMA2): broadcast x = (w*v[k], w*v[k])
// against raw adjacent V pairs from the LDG.128 quads -> 80 FFMA2 per element
// instead of 153 scalar FFMA.

#define NPATCH 512
#define DDIM   12288
#define TPB    256
#define NITER  48            // DDIM / TPB

typedef unsigned long long ull;

#define FMA_F32X2(d, a, b, c) \
    asm("fma.rn.f32x2 %0, %1, %2, %3;" : "=l"(d) : "l"(a), "l"(b), "l"(c))
#define ADD_F32X2(d, a, b) \
    asm("add.rn.f32x2 %0, %1, %2;" : "=l"(d) : "l"(a), "l"(b))
#define PACK_F32X2(out, lo, hi) \
    asm("mov.b64 %0, {%1, %2};" : "=l"(out) : "f"(lo), "f"(hi))
#define UNPACK_F32X2(lo, hi, in) \
    asm("mov.b64 {%0, %1}, %2;" : "=f"(lo), "=f"(hi) : "l"(in))

// scratch rows: 0..152 Gram tri, 153 sum(log sigma), 154 sum(sigma),
// 155 sum(relu(0.3-sigma)^2), 156 sum(V^2), 157 min(sigma)
__device__ float g_scr[158 * NPATCH];
__device__ float g_nll[NPATCH];
__device__ float g_bnd[14];

__global__ __launch_bounds__(TPB, 1) void phase1_kernel(
    const float* __restrict__ x0, const float* __restrict__ mu,
    const float* __restrict__ sigma, const float* __restrict__ V)
{
    const int p = blockIdx.x;
    const int t = threadIdx.x;
    const int b  = p >> 6;
    const int n  = p & 63;
    const int gy = n >> 3;
    const int gx = n & 7;

    const size_t pofs = (size_t)p * DDIM;
    const float4* __restrict__ Vp = (const float4*)(V + pofs * 16);
    const float*  __restrict__ sp = sigma + pofs;
    const float*  __restrict__ mp = mu + pofs;
    const float* __restrict__ x0b =
        x0 + (size_t)b * (3 * 512 * 512) + (size_t)(gy * 64) * 512 + gx * 64 + (t & 63);
    const int t0 = t >> 6;   // d>>6 = 4*i + t0

    // packed accumulators: rows 0..15 -> 72 pairs, row 16 (u) -> 8 pairs
    ull acc2[80];
#pragma unroll
    for (int i = 0; i < 80; i++) acc2[i] = 0ULL;
    ull accv2 = 0ULL;                       // packed sum(V^2)
    float rDr = 0.0f, slog = 0.0f, ssum = 0.0f, srelu = 0.0f;
    float smin = 3.402823466e38f;

    // row start offsets in acc2 and pairs per row
    const int OFFK[17] = {0,1,2,4,6,9,12,16,20,25,30,36,42,49,56,64,72};
    const int PK[17]   = {1,1,2,2,3,3,4,4,5,5,6,6,7,7,8,8,8};

    // preload iteration 0
    float4 va = Vp[t * 4 + 0];
    float4 vb = Vp[t * 4 + 1];
    float4 vc = Vp[t * 4 + 2];
    float4 vd = Vp[t * 4 + 3];
    float s = sp[t];
    float m = mp[t];
    float x = x0b[((t0) >> 6) * (512 * 512) + (t0 & 63) * 512];

#pragma unroll 1
    for (int i = 0; i < NITER; i++) {
        // prefetch next iteration (MLP = 7)
        const int inext = (i + 1 < NITER) ? i + 1 : i;
        const int dn = inext * TPB + t;
        const float4 nva = Vp[dn * 4 + 0];
        const float4 nvb = Vp[dn * 4 + 1];
        const float4 nvc = Vp[dn * 4 + 2];
        const float4 nvd = Vp[dn * 4 + 3];
        const float ns = sp[dn];
        const float nm = mp[dn];
        const int rrn = inext * 4 + t0;
        const float nx = x0b[(rrn >> 6) * (512 * 512) + (rrn & 63) * 512];

        // ---- compute current ----
        const float w = __fdividef(1.0f, s);
        const float r = x - m;

        ull v2[8];
        PACK_F32X2(v2[0], va.x, va.y);
        PACK_F32X2(v2[1], va.z, va.w);
        PACK_F32X2(v2[2], vb.x, vb.y);
        PACK_F32X2(v2[3], vb.z, vb.w);
        PACK_F32X2(v2[4], vc.x, vc.y);
        PACK_F32X2(v2[5], vc.z, vc.w);
        PACK_F32X2(v2[6], vd.x, vd.y);
        PACK_F32X2(v2[7], vd.z, vd.w);

        const float vs0  = va.x, vs1  = va.y, vs2  = va.z, vs3  = va.w;
        const float vs4  = vb.x, vs5  = vb.y, vs6  = vb.z, vs7  = vb.w;
        const float vs8  = vc.x, vs9  = vc.y, vs10 = vc.z, vs11 = vc.w;
        const float vs12 = vd.x, vs13 = vd.y, vs14 = vd.z, vs15 = vd.w;
        const float vsarr[17] = {vs0,vs1,vs2,vs3,vs4,vs5,vs6,vs7,
                                 vs8,vs9,vs10,vs11,vs12,vs13,vs14,vs15, r};

#pragma unroll
        for (int k = 0; k < 17; k++) {
            const float xk = w * vsarr[k];
            ull xk2;
            PACK_F32X2(xk2, xk, xk);
#pragma unroll
            for (int q = 0; q < PK[k]; q++)
                FMA_F32X2(acc2[OFFK[k] + q], xk2, v2[q], acc2[OFFK[k] + q]);
        }

        rDr = fmaf(w * r, r, rDr);

#pragma unroll
        for (int q = 0; q < 8; q++)
            FMA_F32X2(accv2, v2[q], v2[q], accv2);

        slog += __logf(s);
        ssum += s;
        const float rl = fmaxf(0.3f - s, 0.0f);
        srelu = fmaf(rl, rl, srelu);
        smin = fminf(smin, s);

        // rotate
        va = nva; vb = nvb; vc = nvc; vd = nvd;
        s = ns; m = nm; x = nx;
    }

    // ---- intra-warp butterfly reduce (packed) ----
#pragma unroll
    for (int o = 16; o > 0; o >>= 1) {
#pragma unroll
        for (int q = 0; q < 80; q++) {
            const ull other = __shfl_xor_sync(0xffffffffu, acc2[q], o);
            ADD_F32X2(acc2[q], acc2[q], other);
        }
        {
            const ull other = __shfl_xor_sync(0xffffffffu, accv2, o);
            ADD_F32X2(accv2, accv2, other);
        }
        rDr   += __shfl_xor_sync(0xffffffffu, rDr, o);
        slog  += __shfl_xor_sync(0xffffffffu, slog, o);
        ssum  += __shfl_xor_sync(0xffffffffu, ssum, o);
        srelu += __shfl_xor_sync(0xffffffffu, srelu, o);
        smin = fminf(smin, __shfl_xor_sync(0xffffffffu, smin, o));
    }

    __shared__ float red[8][158];
    const int w8 = t >> 5, lane = t & 31;
    if (lane == 0) {
#pragma unroll
        for (int k = 0; k < 16; k++) {
#pragma unroll
            for (int q = 0; q < PK[k]; q++) {
                float lo, hi;
                UNPACK_F32X2(lo, hi, acc2[OFFK[k] + q]);
                const int j0 = 2 * q;
                red[w8][k * (k + 1) / 2 + j0] = lo;
                if (j0 + 1 <= k) red[w8][k * (k + 1) / 2 + j0 + 1] = hi;
            }
        }
#pragma unroll
        for (int q = 0; q < 8; q++) {
            float lo, hi;
            UNPACK_F32X2(lo, hi, acc2[72 + q]);
            red[w8][136 + 2 * q]     = lo;
            red[w8][136 + 2 * q + 1] = hi;
        }
        {
            float lo, hi;
            UNPACK_F32X2(lo, hi, accv2);
            red[w8][156] = lo + hi;
        }
        red[w8][152] = rDr;
        red[w8][153] = slog;
        red[w8][154] = ssum;
        red[w8][155] = srelu;
        red[w8][157] = smin;
    }
    __syncthreads();

    if (t < 158) {
        float v = red[0][t];
        if (t == 157) {
#pragma unroll
            for (int ww = 1; ww < 8; ww++) v = fminf(v, red[ww][t]);
        } else {
#pragma unroll
            for (int ww = 1; ww < 8; ww++) v += red[ww][t];
        }
        g_scr[t * NPATCH + p] = v;
    }
}

// One thread per patch: 16x16 Cholesky + forward solve, fully unrolled.
__global__ __launch_bounds__(256, 1) void phase2_kernel()
{
    const int p = blockIdx.x * 256 + threadIdx.x;

    float L[136];
#pragma unroll
    for (int i = 0; i < 136; i++) L[i] = g_scr[i * NPATCH + p];
    float u[16];
#pragma unroll
    for (int j = 0; j < 16; j++) u[j] = g_scr[(136 + j) * NPATCH + p];
    const float rDr     = g_scr[152 * NPATCH + p];
    const float logdetD = g_scr[153 * NPATCH + p];

#pragma unroll
    for (int k = 0; k < 16; k++) L[k * (k + 1) / 2 + k] += 1.000001f;  // (1+jitter) I

    float invd[16];
    float logdetM = 0.0f;
#pragma unroll
    for (int k = 0; k < 16; k++) {
#pragma unroll
        for (int j = 0; j < k; j++) {
            float sum = L[k * (k + 1) / 2 + j];
#pragma unroll
            for (int i2 = 0; i2 < j; i2++)
                sum -= L[k * (k + 1) / 2 + i2] * L[j * (j + 1) / 2 + i2];
            L[k * (k + 1) / 2 + j] = sum * invd[j];
        }
        float sum = L[k * (k + 1) / 2 + k];
#pragma unroll
        for (int i2 = 0; i2 < k; i2++)
            sum -= L[k * (k + 1) / 2 + i2] * L[k * (k + 1) / 2 + i2];
        const float lkk = sqrtf(sum);
        invd[k] = 1.0f / lkk;
        logdetM += 2.0f * __logf(lkk);
    }

    // quad correction = || L^{-1} u ||^2
    float y[16];
    float corr = 0.0f;
#pragma unroll
    for (int k = 0; k < 16; k++) {
        float sum = u[k];
#pragma unroll
        for (int j = 0; j < k; j++) sum -= L[k * (k + 1) / 2 + j] * y[j];
        y[k] = sum * invd[k];
        corr = fmaf(y[k], y[k], corr);
    }

    const float quad = rDr - corr;
    const float GC = 12288.0f * 1.8378770664093453f;   // d * log(2*pi)
    g_nll[p] = 0.5f * (quad + logdetD + logdetM + GC) * (1.0f / 12288.0f);
}

// Boundary loss: blocks 0..6 -> dy at y = 64*(j+1); blocks 7..13 -> dx at x = 64*(j-6).
__global__ __launch_bounds__(256) void phase3_kernel(const float* __restrict__ mu)
{
    const int j = blockIdx.x;
    const int t = threadIdx.x;
    const bool isdy = (j < 7);
    const int J = isdy ? (j + 1) : (j - 6);

    float sum = 0.0f;
    for (int e = t; e < 12288; e += 256) {
        const int b   = e / 1536;
        const int rem = e - b * 1536;
        const int c   = rem >> 9;       // channel
        const int pos = rem & 511;      // x (dy) or y (dx)
        const int g   = pos >> 6;
        const int q   = pos & 63;
        float hi, lo;
        if (isdy) {
            hi = mu[(size_t)(b * 64 + J * 8 + g) * 12288 + c * 4096 + q];              // py=0
            lo = mu[(size_t)(b * 64 + (J - 1) * 8 + g) * 12288 + c * 4096 + 4032 + q]; // py=63
        } else {
            hi = mu[(size_t)(b * 64 + g * 8 + J) * 12288 + c * 4096 + q * 64];         // px=0
            lo = mu[(size_t)(b * 64 + g * 8 + J - 1) * 12288 + c * 4096 + q * 64 + 63];// px=63
        }
        const float dd = hi - lo;
        sum = fmaf(dd, dd, sum);
    }

    __shared__ float sred[256];
    sred[t] = sum;
    __syncthreads();
    for (int s = 128; s > 0; s >>= 1) {
        if (t < s) sred[t] += sred[t + s];
        __syncthreads();
    }
    if (t == 0) g_bnd[j] = sred[0] * (1.0f / 12288.0f);
}

__global__ __launch_bounds__(256) void phase4_kernel(float* __restrict__ out)
{
    const int t = threadIdx.x;
    float nll  = g_nll[t] + g_nll[t + 256];
    float ssum = g_scr[154 * NPATCH + t] + g_scr[154 * NPATCH + t + 256];
    float srel = g_scr[155 * NPATCH + t] + g_scr[155 * NPATCH + t + 256];
    float sv2  = g_scr[156 * NPATCH + t] + g_scr[156 * NPATCH + t + 256];
    float smin = fminf(g_scr[157 * NPATCH + t], g_scr[157 * NPATCH + t + 256]);

    __shared__ float r0[256], r1[256], r2[256], r3[256], r4[256];
    r0[t] = nll; r1[t] = ssum; r2[t] = srel; r3[t] = sv2; r4[t] = smin;
    __syncthreads();
    for (int s = 128; s > 0; s >>= 1) {
        if (t < s) {
            r0[t] += r0[t + s];
            r1[t] += r1[t + s];
            r2[t] += r2[t + s];
            r3[t] += r3[t + s];
            r4[t]  = fminf(r4[t], r4[t + s]);
        }
        __syncthreads();
    }

    if (t == 0) {
        const float recon = r0[0] * (1.0f / 512.0f);
        float bnd = 0.0f;
#pragma unroll
        for (int jj = 0; jj < 14; jj++) bnd += g_bnd[jj];
        bnd *= (1.0f / 14.0f);
        const float rank = r3[0] * (1.0f / (512.0f * 12288.0f * 16.0f));
        const float sigp = r2[0] * (1.0f / (512.0f * 12288.0f));
        const float msig = r1[0] * (1.0f / (512.0f * 12288.0f));
        const float total = recon + 0.1f * bnd + 0.01f * rank + 0.05f * sigp;
        out[0] = total;
        out[1] = recon;
        out[2] = bnd;
        out[3] = rank;
        out[4] = sigp;
        out[5] = msig;
        out[6] = r4[0];
    }
}

extern "C" void kernel_launch(void* const* d_in, const int* in_sizes, int n_in,
                              void* d_out, int out_size)
{
    const float* x0    = (const float*)d_in[0];
    const float* mu    = (const float*)d_in[1];
    const float* sigma = (const float*)d_in[2];
    const float* V     = (const float*)d_in[3];
    float* out = (float*)d_out;

    phase1_kernel<<<NPATCH, TPB>>>(x0, mu, sigma, V);
    phase2_kernel<<<2, 256>>>();
    phase3_kernel<<<14, 256>>>(mu);
    phase4_kernel<<<1, 256>>>(out);
}